// round 4
// baseline (speedup 1.0000x reference)
#include <cuda_runtime.h>

#define B_  4
#define N_  2048
#define V_  12
#define C_  50
#define P_  16384   /* H*W = 128*128 */
#define RSL 6       /* log2 row stride: 64 floats = 256 B aligned rows */
#define GN_ 8       /* n-items per gather block (= warps per block) */

// Winner keys, encoded key+1 so 0 == "no winner". Statically zero-initialized;
// lift_gather resets each entry to 0 after reading -> clean state every replay.
__device__ int g_winner[B_ * V_ * N_];

// Per-(bv,pixel) RAW logits (50 floats), written only for mask-passing pixels
// (~7%), read only for winning pixels. Softmax is deferred to the gather.
__device__ float g_feat[((size_t)B_ * V_ * P_) << RSL];   // ~201 MB
// Never written -> always zero. Target for views without a winner.
__device__ float g_zero[1 << RSL];

// One thread per pixel: coalesced read of 50 logits (stride P), argmax in
// registers; mask-passing pixels (~7%) pay ONLY a 200B raw-logit store +
// one atomicMax. No exp / no scaling in this kernel.
__global__ __launch_bounds__(256) void argmax_scatter_kernel(
    const float* __restrict__ pred,        // (B,V,C,P)
    const int*   __restrict__ p2p,         // (B,V,P)
    const int*   __restrict__ parts_nb)    // (B,)
{
    int t = blockIdx.x * blockDim.x + threadIdx.x;
    if (t >= B_ * V_ * P_) return;
    int bv = t / P_;
    int p  = t - bv * P_;
    int b  = bv / V_;

    int point = __ldcs(&p2p[t]);
    if (point < 0) return;                 // invalid pixel

    const float* base = pred + (size_t)bv * C_ * P_ + p;
    float x[C_];
    float mx = -3.402823466e+38f;
    int   am = 0;
#pragma unroll
    for (int c = 0; c < C_; c++) {
        x[c] = __ldcs(&base[(size_t)c * P_]);
        if (x[c] > mx) { mx = x[c]; am = c; }   // '>' keeps first occurrence (jnp.argmax)
    }

    int pn = parts_nb[b];
    if (am >= 1 && am <= pn) {
        float* row = g_feat + ((size_t)t << RSL);   // 256B-aligned row
        float4* r4 = (float4*)row;
#pragma unroll
        for (int c4 = 0; c4 < C_ / 4; c4++)         // 48 floats as STG.128
            r4[c4] = make_float4(x[4*c4], x[4*c4+1], x[4*c4+2], x[4*c4+3]);
        ((float2*)row)[24] = make_float2(x[48], x[49]);

        int key = am * P_ + p + 1;             // +1: 0 means "no winner"
        atomicMax(&g_winner[bv * N_ + (point & (N_ - 1))], key);
    }
}

// One WARP per (b,n), 8 warps/block. Branchless row loads (no-winner views
// read g_zero); all 24 row LDGs are independent -> front-batched. Softmax is
// computed here: exp (no max-shift; logits are O(1)) + butterfly sum per view.
__global__ __launch_bounds__(256) void lift_gather_kernel(
    const float* __restrict__ vw,          // (B,V)
    float*       __restrict__ out)         // (B,C,N)
{
    const unsigned FULL = 0xFFFFFFFFu;
    int blk  = blockIdx.x;
    int b    = blk / (N_ / GN_);
    int n0   = (blk - b * (N_ / GN_)) * GN_;
    int wid  = threadIdx.x >> 5;
    int lane = threadIdx.x & 31;
    int n    = n0 + wid;

    __shared__ float s_acc[C_][GN_ + 1];   // +1 pad: conflict-free transpose
    __shared__ float s_dn[GN_];

    // Lanes 0..V-1 read (and reset) winner keys + view weight for their view.
    int key = 0;
    float w = 0.f;
    if (lane < V_) {
        int* wp = &g_winner[(b * V_ + lane) * N_ + n];
        key = *wp;
        *wp = 0;                           // reset for next graph replay
        w = vw[b * V_ + lane];
    }
    unsigned ball = __ballot_sync(FULL, key > 0);
    float denom = fmaxf((float)__popc(ball), 1.f);

    float acc0 = 0.f, acc1 = 0.f;
#pragma unroll
    for (int v = 0; v < V_; v++) {
        int   kv = __shfl_sync(FULL, key, v);
        float wv = __shfl_sync(FULL, w,   v);
        const float* row = (kv > 0)
            ? g_feat + (((size_t)(b * V_ + v) * P_ + ((kv - 1) & (P_ - 1))) << RSL)
            : g_zero;
        float e0 = __expf(row[lane]);                              // c = lane
        float e1 = (lane + 32 < C_) ? __expf(row[lane + 32]) : 0.f; // c = lane+32
        float se = e0 + e1;
#pragma unroll
        for (int s = 16; s >= 1; s >>= 1)
            se += __shfl_xor_sync(FULL, se, s);
        float inv = (kv > 0) ? __fdividef(wv, se) : 0.f;
        acc0 += inv * e0;
        acc1 += inv * e1;
    }

    s_acc[lane][wid] = acc0;
    if (lane + 32 < C_) s_acc[lane + 32][wid] = acc1;
    if (lane == 0) s_dn[wid] = denom;
    __syncthreads();

    // 400 outputs per block, coalesced along n.
#pragma unroll
    for (int i = threadIdx.x; i < C_ * GN_; i += 256) {
        int c = i >> 3, j = i & (GN_ - 1);
        out[((size_t)b * C_ + c) * N_ + n0 + j] = s_acc[c][j] / s_dn[j];
    }
}

extern "C" void kernel_launch(void* const* d_in, const int* in_sizes, int n_in,
                              void* d_out, int out_size) {
    // inputs: 0 points (unused), 1 predictions_2d, 2 rendered_pix_to_point,
    //         3 views_weights, 4 parts_nb
    const float* pred     = (const float*)d_in[1];
    const int*   p2p      = (const int*)  d_in[2];
    const float* vw       = (const float*)d_in[3];
    const int*   parts_nb = (const int*)  d_in[4];
    float*       out      = (float*)d_out;

    argmax_scatter_kernel<<<(B_ * V_ * P_ + 255) / 256, 256>>>(pred, p2p, parts_nb);
    lift_gather_kernel<<<(B_ * N_) / GN_, 256>>>(vw, out);
}

// round 5
// speedup vs baseline: 1.0121x; 1.0121x over previous
#include <cuda_runtime.h>

#define B_  4
#define N_  2048
#define V_  12
#define C_  50
#define P_  16384   /* H*W = 128*128 */
#define RSL 6       /* log2 row stride: 64 floats = 256 B aligned rows */
#define GN_ 8       /* n-items per gather block (= warps per block) */

// Winner keys, encoded key+1 so 0 == "no winner". Statically zero-initialized;
// lift_gather resets each entry to 0 after reading -> clean state every replay.
__device__ int g_winner[B_ * V_ * N_];

// Per-(bv,pixel) RAW logits (50 floats), written only for mask-passing pixels
// (~7%), read only for winning pixels. Softmax is deferred to the gather.
__device__ float g_feat[((size_t)B_ * V_ * P_) << RSL];   // ~201 MB
// Never written -> always zero. Target for views without a winner.
__device__ float g_zero[1 << RSL];

// One thread per pixel: coalesced read of 50 logits (stride P), argmax in
// registers; mask-passing pixels (~7%) pay ONLY a 200B raw-logit store +
// one atomicMax. No exp / no scaling in this kernel.
__global__ __launch_bounds__(256) void argmax_scatter_kernel(
    const float* __restrict__ pred,        // (B,V,C,P)
    const int*   __restrict__ p2p,         // (B,V,P)
    const int*   __restrict__ parts_nb)    // (B,)
{
    int t = blockIdx.x * blockDim.x + threadIdx.x;
    if (t >= B_ * V_ * P_) return;
    int bv = t / P_;
    int p  = t - bv * P_;
    int b  = bv / V_;

    int point = __ldcs(&p2p[t]);
    if (point < 0) return;                 // invalid pixel

    const float* base = pred + (size_t)bv * C_ * P_ + p;
    float x[C_];
    float mx = -3.402823466e+38f;
    int   am = 0;
#pragma unroll
    for (int c = 0; c < C_; c++) {
        x[c] = __ldcs(&base[(size_t)c * P_]);
        if (x[c] > mx) { mx = x[c]; am = c; }   // '>' keeps first occurrence (jnp.argmax)
    }

    int pn = parts_nb[b];
    if (am >= 1 && am <= pn) {
        float* row = g_feat + ((size_t)t << RSL);   // 256B-aligned row
        float4* r4 = (float4*)row;
#pragma unroll
        for (int c4 = 0; c4 < C_ / 4; c4++)         // 48 floats as STG.128
            r4[c4] = make_float4(x[4*c4], x[4*c4+1], x[4*c4+2], x[4*c4+3]);
        ((float2*)row)[24] = make_float2(x[48], x[49]);

        int key = am * P_ + p + 1;             // +1: 0 means "no winner"
        atomicMax(&g_winner[bv * N_ + (point & (N_ - 1))], key);
    }
}

// One WARP per (b,n), 8 warps/block. TWO PHASES:
//   phase 1: all 24 independent row loads into registers (front-batched, MLP~24)
//   phase 2: exp + per-view butterfly sums + weighted accumulate
// No-winner views read g_zero (branchless pointer select).
__global__ __launch_bounds__(256) void lift_gather_kernel(
    const float* __restrict__ vw,          // (B,V)
    float*       __restrict__ out)         // (B,C,N)
{
    const unsigned FULL = 0xFFFFFFFFu;
    int blk  = blockIdx.x;
    int b    = blk / (N_ / GN_);
    int n0   = (blk - b * (N_ / GN_)) * GN_;
    int wid  = threadIdx.x >> 5;
    int lane = threadIdx.x & 31;
    int n    = n0 + wid;

    __shared__ float s_acc[C_][GN_ + 1];   // +1 pad: conflict-free transpose
    __shared__ float s_dn[GN_];

    // Lanes 0..V-1 read (and reset) winner keys + view weight for their view.
    int key = 0;
    float w = 0.f;
    if (lane < V_) {
        int* wp = &g_winner[(b * V_ + lane) * N_ + n];
        key = *wp;
        *wp = 0;                           // reset for next graph replay
        w = vw[b * V_ + lane];
    }
    unsigned ball = __ballot_sync(FULL, key > 0);
    float denom = fmaxf((float)__popc(ball), 1.f);

    // ---- phase 1: batched loads, no consuming arithmetic in between ----
    float e0[V_], e1[V_];
#pragma unroll
    for (int v = 0; v < V_; v++) {
        int kv = __shfl_sync(FULL, key, v);
        const float* row = (kv > 0)
            ? g_feat + (((size_t)(b * V_ + v) * P_ + ((kv - 1) & (P_ - 1))) << RSL)
            : g_zero;
        e0[v] = __ldg(&row[lane]);         // c = lane
        e1[v] = __ldg(&row[lane + 32]);    // c = lane+32 (pad cols are 0)
    }

    // ---- phase 2: softmax + weighted accumulate (12 independent chains) ----
    float acc0 = 0.f, acc1 = 0.f;
#pragma unroll
    for (int v = 0; v < V_; v++) {
        int   kv = __shfl_sync(FULL, key, v);
        float wv = __shfl_sync(FULL, w,   v);
        float x0 = __expf(e0[v]);
        float x1 = (lane + 32 < C_) ? __expf(e1[v]) : 0.f;
        float se = x0 + x1;
#pragma unroll
        for (int s = 16; s >= 1; s >>= 1)
            se += __shfl_xor_sync(FULL, se, s);
        float inv = (kv > 0) ? __fdividef(wv, se) : 0.f;
        acc0 += inv * x0;
        acc1 += inv * x1;
    }

    s_acc[lane][wid] = acc0;
    if (lane + 32 < C_) s_acc[lane + 32][wid] = acc1;
    if (lane == 0) s_dn[wid] = denom;
    __syncthreads();

    // 400 outputs per block, coalesced along n.
#pragma unroll
    for (int i = threadIdx.x; i < C_ * GN_; i += 256) {
        int c = i >> 3, j = i & (GN_ - 1);
        out[((size_t)b * C_ + c) * N_ + n0 + j] = s_acc[c][j] / s_dn[j];
    }
}

extern "C" void kernel_launch(void* const* d_in, const int* in_sizes, int n_in,
                              void* d_out, int out_size) {
    // inputs: 0 points (unused), 1 predictions_2d, 2 rendered_pix_to_point,
    //         3 views_weights, 4 parts_nb
    const float* pred     = (const float*)d_in[1];
    const int*   p2p      = (const int*)  d_in[2];
    const float* vw       = (const float*)d_in[3];
    const int*   parts_nb = (const int*)  d_in[4];
    float*       out      = (float*)d_out;

    argmax_scatter_kernel<<<(B_ * V_ * P_ + 255) / 256, 256>>>(pred, p2p, parts_nb);
    lift_gather_kernel<<<(B_ * N_) / GN_, 256>>>(vw, out);
}

// round 6
// speedup vs baseline: 1.0442x; 1.0317x over previous
#include <cuda_runtime.h>

#define B_  4
#define N_  2048
#define V_  12
#define C_  50
#define P_  16384   /* H*W = 128*128 */
#define RSL 6       /* log2 row stride: 64 floats = 256 B aligned rows */
#define GN_ 8       /* n-items per gather block (= warps per block) */

// Winner keys, encoded key+1 so 0 == "no winner". Statically zero-initialized;
// lift_gather resets each entry to 0 after reading -> clean state every replay.
__device__ int g_winner[B_ * V_ * N_];

// Per-(bv,pixel) rows: K1 writes RAW logits for mask-passing pixels (~7%);
// K2 overwrites winner rows in place with w_v * softmax. Pad cols stay 0.
__device__ float g_feat[((size_t)B_ * V_ * P_) << RSL];   // ~201 MB
// Never written -> always zero. Target for views without a winner.
__device__ float g_zero[1 << RSL];

// K1 — one thread per pixel: coalesced read of 50 logits (stride P), argmax in
// registers; mask-passing pixels pay ONLY a 200B raw-logit store + atomicMax.
__global__ __launch_bounds__(256) void argmax_scatter_kernel(
    const float* __restrict__ pred,        // (B,V,C,P)
    const int*   __restrict__ p2p,         // (B,V,P)
    const int*   __restrict__ parts_nb)    // (B,)
{
    int t = blockIdx.x * blockDim.x + threadIdx.x;
    if (t >= B_ * V_ * P_) return;
    int bv = t / P_;
    int p  = t - bv * P_;
    int b  = bv / V_;

    int point = __ldcs(&p2p[t]);
    if (point < 0) return;                 // invalid pixel

    const float* base = pred + (size_t)bv * C_ * P_ + p;
    float x[C_];
    float mx = -3.402823466e+38f;
    int   am = 0;
#pragma unroll
    for (int c = 0; c < C_; c++) {
        x[c] = __ldcs(&base[(size_t)c * P_]);
        if (x[c] > mx) { mx = x[c]; am = c; }   // '>' keeps first occurrence (jnp.argmax)
    }

    int pn = parts_nb[b];
    if (am >= 1 && am <= pn) {
        float* row = g_feat + ((size_t)t << RSL);   // 256B-aligned row
        float4* r4 = (float4*)row;
#pragma unroll
        for (int c4 = 0; c4 < C_ / 4; c4++)         // 48 floats as STG.128
            r4[c4] = make_float4(x[4*c4], x[4*c4+1], x[4*c4+2], x[4*c4+3]);
        ((float2*)row)[24] = make_float2(x[48], x[49]);

        int key = am * P_ + p + 1;             // +1: 0 means "no winner"
        atomicMax(&g_winner[bv * N_ + (point & (N_ - 1))], key);
    }
}

// K2 — one warp per winner slot: normalize the winning pixel's raw-logit row
// in place to w_v * softmax. Dense non-divergent warps; slots without a
// winner exit after one broadcast load. Each winning pixel belongs to exactly
// one (bv, n) slot, so in-place rewrites never conflict.
__global__ __launch_bounds__(256) void softmax_rows_kernel(
    const float* __restrict__ vw)          // (B,V)
{
    const unsigned FULL = 0xFFFFFFFFu;
    int slot = blockIdx.x * 8 + (threadIdx.x >> 5);   // (bv, n) slot
    int lane = threadIdx.x & 31;

    int key = g_winner[slot];              // same addr all lanes -> broadcast
    if (key <= 0) return;

    int bv = slot / N_;
    int p  = (key - 1) & (P_ - 1);
    float* row = g_feat + (((size_t)bv * P_ + p) << RSL);

    float x0 = row[lane];
    float x1 = row[lane + 32];
    float e0 = __expf(x0);                               // c = lane
    float e1 = (lane + 32 < C_) ? __expf(x1) : 0.f;      // pads contribute 0
    float se = e0 + e1;
#pragma unroll
    for (int s = 16; s >= 1; s >>= 1)
        se += __shfl_xor_sync(FULL, se, s);
    float scale = __fdividef(vw[bv], se);

    row[lane]      = e0 * scale;
    row[lane + 32] = e1 * scale;           // pads written as 0, stay safe
}

// K3 — one WARP per (b,n), 8 warps/block (R3-proven form). Branchless: views
// without a winner read g_zero; all 24 row loads independent. Rows are
// pre-scaled weighted probs -> plain adds. Output transposed via smem.
__global__ __launch_bounds__(256) void lift_gather_kernel(
    float* __restrict__ out)               // (B,C,N)
{
    int blk  = blockIdx.x;
    int b    = blk / (N_ / GN_);
    int n0   = (blk - b * (N_ / GN_)) * GN_;
    int wid  = threadIdx.x >> 5;
    int lane = threadIdx.x & 31;
    int n    = n0 + wid;

    __shared__ float s_acc[C_][GN_ + 1];   // +1 pad: conflict-free transpose
    __shared__ float s_dn[GN_];

    // Lanes 0..V-1 read (and reset) winner keys for their view.
    int key = 0;
    if (lane < V_) {
        int* wp = &g_winner[(b * V_ + lane) * N_ + n];
        key = *wp;
        *wp = 0;                           // reset for next graph replay
    }
    unsigned ball = __ballot_sync(0xFFFFFFFFu, key > 0);
    float denom = fmaxf((float)__popc(ball), 1.f);

    float acc0 = 0.f, acc1 = 0.f;
#pragma unroll
    for (int v = 0; v < V_; v++) {
        int kv = __shfl_sync(0xFFFFFFFFu, key, v);
        const float* row = (kv > 0)
            ? g_feat + (((size_t)(b * V_ + v) * P_ + ((kv - 1) & (P_ - 1))) << RSL)
            : g_zero;
        acc0 += row[lane];                 // c = lane
        acc1 += row[lane + 32];            // c = lane+32 (pad cols are 0)
    }

    s_acc[lane][wid] = acc0;
    if (lane + 32 < C_) s_acc[lane + 32][wid] = acc1;
    if (lane == 0) s_dn[wid] = denom;
    __syncthreads();

    // 400 outputs per block, coalesced along n.
#pragma unroll
    for (int i = threadIdx.x; i < C_ * GN_; i += 256) {
        int c = i >> 3, j = i & (GN_ - 1);
        out[((size_t)b * C_ + c) * N_ + n0 + j] = s_acc[c][j] / s_dn[j];
    }
}

extern "C" void kernel_launch(void* const* d_in, const int* in_sizes, int n_in,
                              void* d_out, int out_size) {
    // inputs: 0 points (unused), 1 predictions_2d, 2 rendered_pix_to_point,
    //         3 views_weights, 4 parts_nb
    const float* pred     = (const float*)d_in[1];
    const int*   p2p      = (const int*)  d_in[2];
    const float* vw       = (const float*)d_in[3];
    const int*   parts_nb = (const int*)  d_in[4];
    float*       out      = (float*)d_out;

    argmax_scatter_kernel<<<(B_ * V_ * P_ + 255) / 256, 256>>>(pred, p2p, parts_nb);
    softmax_rows_kernel<<<(B_ * V_ * N_) / 8, 256>>>(vw);
    lift_gather_kernel<<<(B_ * N_) / GN_, 256>>>(out);
}

// round 7
// speedup vs baseline: 1.1101x; 1.0631x over previous
#include <cuda_runtime.h>

#define B_  4
#define N_  2048
#define V_  12
#define C_  50
#define P_  16384   /* H*W = 128*128 */
#define RSL 6       /* log2 row stride: 64 floats = 256 B aligned rows */
#define GN_ 8       /* n-items per lift block (= warps per block) */

// Winner keys, encoded key+1 so 0 == "no winner". Statically zero-initialized;
// lift resets each entry to 0 after reading -> clean state every replay.
__device__ int g_winner[B_ * V_ * N_];

// Per-(bv,pixel) RAW logit rows (50 floats used, 64 stride), written only for
// mask-passing pixels (~7%). Cols 50..63 never written -> always zero.
__device__ float g_feat[((size_t)B_ * V_ * P_) << RSL];   // ~201 MB
// Never written -> always zero. Target for views without a winner.
__device__ float g_zero[1 << RSL];

// K1 — one thread per pixel, TWO PASSES to keep regs low (occupancy/MLP):
// pass 1: streaming argmax over 50 stride-P logits, no x[] array;
// pass 2 (mask-passing ~7% only): re-read the 50 logits, store 200B row,
// atomicMax the winner key.
__global__ __launch_bounds__(256) void argmax_scatter_kernel(
    const float* __restrict__ pred,        // (B,V,C,P)
    const int*   __restrict__ p2p,         // (B,V,P)
    const int*   __restrict__ parts_nb)    // (B,)
{
    int t = blockIdx.x * blockDim.x + threadIdx.x;
    if (t >= B_ * V_ * P_) return;
    int bv = t >> 14;                      // / P_
    int p  = t & (P_ - 1);
    int b  = bv / V_;

    int point = __ldcs(&p2p[t]);
    if (point < 0) return;                 // invalid pixel
    int pn = parts_nb[b];

    const float* base = pred + (size_t)bv * C_ * P_ + p;
    float mx = -3.402823466e+38f;
    int   am = 0;
#pragma unroll
    for (int c = 0; c < C_; c++) {
        float xc = __ldcs(&base[(size_t)c * P_]);
        if (xc > mx) { mx = xc; am = c; }  // '>' keeps first occurrence (jnp.argmax)
    }

    if (am >= 1 && am <= pn) {
        float* row = g_feat + ((size_t)t << RSL);   // 256B-aligned row
        float4* r4 = (float4*)row;
#pragma unroll
        for (int c4 = 0; c4 < C_ / 4; c4++) {       // re-read + STG.128
            float4 v;
            v.x = __ldg(&base[(size_t)(4*c4+0) * P_]);
            v.y = __ldg(&base[(size_t)(4*c4+1) * P_]);
            v.z = __ldg(&base[(size_t)(4*c4+2) * P_]);
            v.w = __ldg(&base[(size_t)(4*c4+3) * P_]);
            r4[c4] = v;
        }
        ((float2*)row)[24] = make_float2(__ldg(&base[(size_t)48 * P_]),
                                         __ldg(&base[(size_t)49 * P_]));

        int key = am * P_ + p + 1;             // +1: 0 means "no winner"
        atomicMax(&g_winner[bv * N_ + (point & (N_ - 1))], key);
    }
}

// K2 — fused lift: one WARP per (b,n), 8 warps/block.
//   phase 0: lanes 0..V-1 read+reset winner keys, read view weights
//   phase 1: 24 independent LDG->STS pairs stage the 12 rows into smem
//            (every lane touches only its own smem slots -> no sync needed)
//   phase 2: per-view softmax from smem (exp, butterfly, div) + accumulate
//   phase 3: smem transpose, coalesced (B,C,N) writes
__global__ __launch_bounds__(256) void lift_kernel(
    const float* __restrict__ vw,          // (B,V)
    float*       __restrict__ out)         // (B,C,N)
{
    const unsigned FULL = 0xFFFFFFFFu;
    int blk  = blockIdx.x;
    int b    = blk / (N_ / GN_);
    int n0   = (blk - b * (N_ / GN_)) * GN_;
    int wid  = threadIdx.x >> 5;
    int lane = threadIdx.x & 31;
    int n    = n0 + wid;

    __shared__ float s_row[GN_][V_][64];   // 24.5 KB staged rows
    __shared__ float s_acc[C_][GN_ + 1];   // +1 pad: conflict-free transpose
    __shared__ float s_dn[GN_];

    // phase 0
    int key = 0;
    float w = 0.f;
    if (lane < V_) {
        int* wp = &g_winner[(b * V_ + lane) * N_ + n];
        key = *wp;
        *wp = 0;                           // reset for next graph replay
        w = vw[b * V_ + lane];
    }
    unsigned ball = __ballot_sync(FULL, key > 0);
    float denom = fmaxf((float)__popc(ball), 1.f);

    // phase 1: stage all 12 rows (24 independent loads), same-lane smem slots
#pragma unroll
    for (int v = 0; v < V_; v++) {
        int kv = __shfl_sync(FULL, key, v);
        const float* row = (kv > 0)
            ? g_feat + (((size_t)(b * V_ + v) * P_ + ((kv - 1) & (P_ - 1))) << RSL)
            : g_zero;
        s_row[wid][v][lane]      = __ldg(&row[lane]);
        s_row[wid][v][lane + 32] = __ldg(&row[lane + 32]);
    }

    // phase 2: softmax per view from smem + weighted accumulate
    float acc0 = 0.f, acc1 = 0.f;
#pragma unroll
    for (int v = 0; v < V_; v++) {
        int   kv = __shfl_sync(FULL, key, v);
        float wv = __shfl_sync(FULL, w,   v);
        float e0 = __expf(s_row[wid][v][lane]);
        float e1 = (lane + 32 < C_) ? __expf(s_row[wid][v][lane + 32]) : 0.f;
        float se = e0 + e1;
#pragma unroll
        for (int s = 16; s >= 1; s >>= 1)
            se += __shfl_xor_sync(FULL, se, s);
        float inv = (kv > 0) ? __fdividef(wv, se) : 0.f;
        acc0 += inv * e0;
        acc1 += inv * e1;
    }

    s_acc[lane][wid] = acc0;
    if (lane + 32 < C_) s_acc[lane + 32][wid] = acc1;
    if (lane == 0) s_dn[wid] = denom;
    __syncthreads();

    // phase 3: 400 outputs per block, coalesced along n
#pragma unroll
    for (int i = threadIdx.x; i < C_ * GN_; i += 256) {
        int c = i >> 3, j = i & (GN_ - 1);
        out[((size_t)b * C_ + c) * N_ + n0 + j] = s_acc[c][j] / s_dn[j];
    }
}

extern "C" void kernel_launch(void* const* d_in, const int* in_sizes, int n_in,
                              void* d_out, int out_size) {
    // inputs: 0 points (unused), 1 predictions_2d, 2 rendered_pix_to_point,
    //         3 views_weights, 4 parts_nb
    const float* pred     = (const float*)d_in[1];
    const int*   p2p      = (const int*)  d_in[2];
    const float* vw       = (const float*)d_in[3];
    const int*   parts_nb = (const int*)  d_in[4];
    float*       out      = (float*)d_out;

    argmax_scatter_kernel<<<(B_ * V_ * P_ + 255) / 256, 256>>>(pred, p2p, parts_nb);
    lift_kernel<<<(B_ * N_) / GN_, 256>>>(vw, out);
}

// round 8
// speedup vs baseline: 1.6277x; 1.4663x over previous
#include <cuda_runtime.h>

#define B_  4
#define N_  2048
#define V_  12
#define C_  50
#define P_  16384   /* H*W = 128*128 */
#define RSL 6       /* log2 row stride: 64 floats = 256 B aligned rows */
#define GN_ 8       /* n-items per lift block (= warps per block) */

// Winner keys, encoded key+1 so 0 == "no winner". Statically zero-initialized;
// lift resets each entry to 0 after reading -> clean state every replay.
__device__ int g_winner[B_ * V_ * N_];

// Per-(bv,pixel) RAW logit rows (50 floats used, 64 stride), written only for
// mask-passing pixels (~7%). Cols 50..63 never written -> always zero.
__device__ float g_feat[((size_t)B_ * V_ * P_) << RSL];   // ~201 MB
// Never written -> always zero. Target for views without a winner.
__device__ float g_zero[1 << RSL];

// K1 — one thread per pixel, single pass, x[50] in registers (R6 form, 32us
// measured). NO early returns: p2p / parts_nb / pred loads all issue
// unconditionally so the warp never serializes p2p-latency -> pred-latency;
// validity is folded into the final mask.
__global__ __launch_bounds__(256) void argmax_scatter_kernel(
    const float* __restrict__ pred,        // (B,V,C,P)
    const int*   __restrict__ p2p,         // (B,V,P)
    const int*   __restrict__ parts_nb)    // (B,)
{
    int t = blockIdx.x * blockDim.x + threadIdx.x;
    int bv = t >> 14;                      // / P_
    int p  = t & (P_ - 1);
    int b  = bv / V_;

    int point = __ldcs(&p2p[t]);           // issued alongside pred loads
    int pn    = parts_nb[b];

    const float* base = pred + (size_t)bv * C_ * P_ + p;
    float x[C_];
    float mx = -3.402823466e+38f;
    int   am = 0;
#pragma unroll
    for (int c = 0; c < C_; c++) {
        x[c] = __ldcs(&base[(size_t)c * P_]);
        if (x[c] > mx) { mx = x[c]; am = c; }   // '>' keeps first occurrence (jnp.argmax)
    }

    if (point >= 0 && am >= 1 && am <= pn) {
        float* row = g_feat + ((size_t)t << RSL);   // 256B-aligned row
        float4* r4 = (float4*)row;
#pragma unroll
        for (int c4 = 0; c4 < C_ / 4; c4++)         // 48 floats as STG.128
            r4[c4] = make_float4(x[4*c4], x[4*c4+1], x[4*c4+2], x[4*c4+3]);
        ((float2*)row)[24] = make_float2(x[48], x[49]);

        int key = am * P_ + p + 1;             // +1: 0 means "no winner"
        atomicMax(&g_winner[bv * N_ + (point & (N_ - 1))], key);
    }
}

// K2 — fused lift (R7-measured 12.8us): one WARP per (b,n), 8 warps/block.
//   phase 0: lanes 0..V-1 read+reset winner keys, read view weights
//   phase 1: 24 independent LDG->STS pairs stage the 12 rows into smem
//   phase 2: per-view softmax from smem (exp, butterfly, div) + accumulate
//   phase 3: smem transpose, coalesced (B,C,N) writes
__global__ __launch_bounds__(256) void lift_kernel(
    const float* __restrict__ vw,          // (B,V)
    float*       __restrict__ out)         // (B,C,N)
{
    const unsigned FULL = 0xFFFFFFFFu;
    int blk  = blockIdx.x;
    int b    = blk / (N_ / GN_);
    int n0   = (blk - b * (N_ / GN_)) * GN_;
    int wid  = threadIdx.x >> 5;
    int lane = threadIdx.x & 31;
    int n    = n0 + wid;

    __shared__ float s_row[GN_][V_][64];   // 24.5 KB staged rows
    __shared__ float s_acc[C_][GN_ + 1];   // +1 pad: conflict-free transpose
    __shared__ float s_dn[GN_];

    // phase 0
    int key = 0;
    float w = 0.f;
    if (lane < V_) {
        int* wp = &g_winner[(b * V_ + lane) * N_ + n];
        key = *wp;
        *wp = 0;                           // reset for next graph replay
        w = vw[b * V_ + lane];
    }
    unsigned ball = __ballot_sync(FULL, key > 0);
    float denom = fmaxf((float)__popc(ball), 1.f);

    // phase 1: stage all 12 rows (24 independent loads), same-lane smem slots
#pragma unroll
    for (int v = 0; v < V_; v++) {
        int kv = __shfl_sync(FULL, key, v);
        const float* row = (kv > 0)
            ? g_feat + (((size_t)(b * V_ + v) * P_ + ((kv - 1) & (P_ - 1))) << RSL)
            : g_zero;
        s_row[wid][v][lane]      = __ldg(&row[lane]);
        s_row[wid][v][lane + 32] = __ldg(&row[lane + 32]);
    }

    // phase 2: softmax per view from smem + weighted accumulate
    float acc0 = 0.f, acc1 = 0.f;
#pragma unroll
    for (int v = 0; v < V_; v++) {
        int   kv = __shfl_sync(FULL, key, v);
        float wv = __shfl_sync(FULL, w,   v);
        float e0 = __expf(s_row[wid][v][lane]);
        float e1 = (lane + 32 < C_) ? __expf(s_row[wid][v][lane + 32]) : 0.f;
        float se = e0 + e1;
#pragma unroll
        for (int s = 16; s >= 1; s >>= 1)
            se += __shfl_xor_sync(FULL, se, s);
        float inv = (kv > 0) ? __fdividef(wv, se) : 0.f;
        acc0 += inv * e0;
        acc1 += inv * e1;
    }

    s_acc[lane][wid] = acc0;
    if (lane + 32 < C_) s_acc[lane + 32][wid] = acc1;
    if (lane == 0) s_dn[wid] = denom;
    __syncthreads();

    // phase 3: 400 outputs per block, coalesced along n
#pragma unroll
    for (int i = threadIdx.x; i < C_ * GN_; i += 256) {
        int c = i >> 3, j = i & (GN_ - 1);
        out[((size_t)b * C_ + c) * N_ + n0 + j] = s_acc[c][j] / s_dn[j];
    }
}

extern "C" void kernel_launch(void* const* d_in, const int* in_sizes, int n_in,
                              void* d_out, int out_size) {
    // inputs: 0 points (unused), 1 predictions_2d, 2 rendered_pix_to_point,
    //         3 views_weights, 4 parts_nb
    const float* pred     = (const float*)d_in[1];
    const int*   p2p      = (const int*)  d_in[2];
    const float* vw       = (const float*)d_in[3];
    const int*   parts_nb = (const int*)  d_in[4];
    float*       out      = (float*)d_out;

    argmax_scatter_kernel<<<(B_ * V_ * P_) / 256, 256>>>(pred, p2p, parts_nb);
    lift_kernel<<<(B_ * N_) / GN_, 256>>>(vw, out);
}